// round 4
// baseline (speedup 1.0000x reference)
#include <cuda_runtime.h>
#include <cuda_bf16.h>

// ---------------- problem constants (fixed by the dataset) ----------------
#define MAXN 100000
#define MAXE 1600000
#define HID 64

// ---------------- device scratch (no allocation allowed) ------------------
__device__ float d_bufA[MAXN * HID];
__device__ float d_bufB[MAXN * HID];
__device__ float d_dis[MAXN];          // deg^{-1/2}
__device__ int   d_cnt[MAXN];          // in-degree (without self loop)
__device__ int   d_off[MAXN + 1];      // CSR offsets
__device__ int   d_cursor[MAXN];       // fill cursors
__device__ int   d_csrc[MAXE];         // CSR: src node per incoming edge slot
__device__ int   d_partials[128];      // scan block partials
__device__ float d_pooled[64 * HID];   // per-graph means
__device__ int   g_is64;               // 1 if index tensors are int64

// ---------------- index dtype detection -----------------------------------
// edge_index values are uniform in [0, N). If the buffer is int64, every
// 8-byte word is < N. If it's int32, a word combines two random int32s and is
// >= 2^32 unless the high half is 0 (p ~ 1e-5 per word). 16 words -> certain.
__global__ void k_detect(const void* __restrict__ ei) {
    const long long* p = (const long long*)ei;
    int ok = 1;
#pragma unroll
    for (int i = 0; i < 16; i++) {
        long long v = p[i];
        if (v < 0 || v >= MAXN) ok = 0;
    }
    g_is64 = ok;
}

__device__ __forceinline__ int load_idx(const void* p, long long i) {
    return g_is64 ? (int)((const long long*)p)[i] : ((const int*)p)[i];
}
__device__ __forceinline__ long long load_batch(const void* p, int i) {
    return g_is64 ? ((const long long*)p)[i] : (long long)((const int*)p)[i];
}

// ---------------- CSR build ----------------

__global__ void k_zero_cnt(int N) {
    int i = blockIdx.x * blockDim.x + threadIdx.x;
    if (i < N) d_cnt[i] = 0;
}

__global__ void k_count(const void* __restrict__ ei, int E) {
    int e = blockIdx.x * blockDim.x + threadIdx.x;
    if (e < E) {
        int dst = load_idx(ei, (long long)E + e);
        atomicAdd(&d_cnt[dst], 1);
    }
}

// per-1024 block sums + dis = rsqrt(deg+1)
__global__ void k_blocksum(int N) {
    __shared__ int sh[256];
    int b = blockIdx.x, t = threadIdx.x;
    int base = b * 1024;
    int s = 0;
#pragma unroll
    for (int i = 0; i < 4; i++) {
        int idx = base + t + i * 256;
        if (idx < N) {
            int c = d_cnt[idx];
            s += c;
            d_dis[idx] = rsqrtf((float)(c + 1));   // self loop included, deg>=1
        }
    }
    sh[t] = s;
    __syncthreads();
    for (int o = 128; o > 0; o >>= 1) {
        if (t < o) sh[t] += sh[t + o];
        __syncthreads();
    }
    if (t == 0) d_partials[b] = sh[0];
}

// single-block exclusive scan of the (<=128) block partials; also off[N]=E
__global__ void k_scanpart(int nb, int N, int E) {
    __shared__ int sh[128];
    int t = threadIdx.x;
    sh[t] = (t < nb) ? d_partials[t] : 0;
    __syncthreads();
    for (int o = 1; o < 128; o <<= 1) {
        int v = (t >= o) ? sh[t - o] : 0;
        __syncthreads();
        sh[t] += v;
        __syncthreads();
    }
    if (t < nb) d_partials[t] = (t == 0) ? 0 : sh[t - 1];
    if (t == 0) d_off[N] = E;
}

// per-block 1024-wide exclusive scan -> CSR offsets + cursors
__global__ void k_scanblock(int N) {
    __shared__ int sh[1024];
    int b = blockIdx.x, t = threadIdx.x;
    int gid = b * 1024 + t;
    int v = (gid < N) ? d_cnt[gid] : 0;
    sh[t] = v;
    __syncthreads();
    for (int o = 1; o < 1024; o <<= 1) {
        int u = (t >= o) ? sh[t - o] : 0;
        __syncthreads();
        sh[t] += u;
        __syncthreads();
    }
    if (gid < N) {
        int excl = sh[t] - v + d_partials[b];
        d_off[gid] = excl;
        d_cursor[gid] = excl;
    }
}

__global__ void k_fill(const void* __restrict__ ei, int E) {
    int e = blockIdx.x * blockDim.x + threadIdx.x;
    if (e < E) {
        int dst = load_idx(ei, (long long)E + e);
        int src = load_idx(ei, e);
        int p = atomicAdd(&d_cursor[dst], 1);
        d_csrc[p] = src;
    }
}

// ---------------- GEMM: C[N x 64] = A[N x K] * B[K x 64] ----------------
// BM=64, BN=64, BK=16, 256 threads, 4x4 register tile per thread.
// src selects input (0: external pointer A, 1: d_bufA, 2: d_bufB)
// dst selects output (1: d_bufA, 2: d_bufB)
__global__ __launch_bounds__(256) void k_gemm(const float* __restrict__ Aext,
                                              const int src, const int dst,
                                              const float* __restrict__ B,
                                              int N, int K) {
    const float* A = (src == 0) ? Aext : (src == 1 ? d_bufA : d_bufB);
    float* C = (dst == 1) ? d_bufA : d_bufB;

    __shared__ float As[16][64];
    __shared__ float Bs[16][64];
    int block_row = blockIdx.x * 64;
    int t = threadIdx.x;
    int tx = t & 15;          // col group
    int ty = t >> 4;          // row group
    float acc[4][4] = {};

    for (int k0 = 0; k0 < K; k0 += 16) {
        {
            int m = t >> 2;            // 0..63
            int kk = (t & 3) * 4;      // 0,4,8,12
            int row = block_row + m;
            float4 v = make_float4(0.f, 0.f, 0.f, 0.f);
            if (row < N) v = *(const float4*)&A[(long long)row * K + k0 + kk];
            As[kk + 0][m] = v.x;
            As[kk + 1][m] = v.y;
            As[kk + 2][m] = v.z;
            As[kk + 3][m] = v.w;
        }
        {
            int kk = t >> 4;           // 0..15
            int n = (t & 15) * 4;      // 0..60
            float4 v = *(const float4*)&B[(k0 + kk) * 64 + n];
            *(float4*)&Bs[kk][n] = v;
        }
        __syncthreads();

#pragma unroll
        for (int kk = 0; kk < 16; kk++) {
            float4 a4 = *(float4*)&As[kk][ty * 4];
            float4 b4 = *(float4*)&Bs[kk][tx * 4];
            float a[4] = {a4.x, a4.y, a4.z, a4.w};
            float bb[4] = {b4.x, b4.y, b4.z, b4.w};
#pragma unroll
            for (int r = 0; r < 4; r++)
#pragma unroll
                for (int c = 0; c < 4; c++)
                    acc[r][c] = fmaf(a[r], bb[c], acc[r][c]);
        }
        __syncthreads();
    }

#pragma unroll
    for (int r = 0; r < 4; r++) {
        int row = block_row + ty * 4 + r;
        if (row < N) {
            *(float4*)&C[(long long)row * 64 + tx * 4] =
                make_float4(acc[r][0], acc[r][1], acc[r][2], acc[r][3]);
        }
    }
}

// ---------------- aggregation: out[i] = sum_{j in N(i)} w_ij * hin[j] + b --
// one warp per node; lane handles features (lane, lane+32)
// src/dst: 1 = d_bufA, 2 = d_bufB
__global__ __launch_bounds__(256) void k_agg(const int src, const int dst,
                                             const float* __restrict__ bias,
                                             int N, const int do_relu) {
    const float* hin = (src == 1) ? d_bufA : d_bufB;
    float* hout = (dst == 1) ? d_bufA : d_bufB;

    int node = blockIdx.x * 8 + (threadIdx.x >> 5);
    if (node >= N) return;
    int lane = threadIdx.x & 31;
    float di = d_dis[node];
    // self loop: weight = dis[i]^2
    float a0 = di * di * __ldg(&hin[(long long)node * 64 + lane]);
    float a1 = di * di * __ldg(&hin[(long long)node * 64 + lane + 32]);
    int j = __ldg(&d_off[node]);
    int jend = __ldg(&d_off[node + 1]);

    for (; j + 4 <= jend; j += 4) {
        int sa = __ldg(&d_csrc[j + 0]);
        int sb = __ldg(&d_csrc[j + 1]);
        int sc = __ldg(&d_csrc[j + 2]);
        int sd = __ldg(&d_csrc[j + 3]);
        float wa = __ldg(&d_dis[sa]) * di;
        float wb = __ldg(&d_dis[sb]) * di;
        float wc = __ldg(&d_dis[sc]) * di;
        float wd = __ldg(&d_dis[sd]) * di;
        float ha0 = __ldg(&hin[(long long)sa * 64 + lane]);
        float hb0 = __ldg(&hin[(long long)sb * 64 + lane]);
        float hc0 = __ldg(&hin[(long long)sc * 64 + lane]);
        float hd0 = __ldg(&hin[(long long)sd * 64 + lane]);
        float ha1 = __ldg(&hin[(long long)sa * 64 + lane + 32]);
        float hb1 = __ldg(&hin[(long long)sb * 64 + lane + 32]);
        float hc1 = __ldg(&hin[(long long)sc * 64 + lane + 32]);
        float hd1 = __ldg(&hin[(long long)sd * 64 + lane + 32]);
        a0 = fmaf(wa, ha0, a0); a1 = fmaf(wa, ha1, a1);
        a0 = fmaf(wb, hb0, a0); a1 = fmaf(wb, hb1, a1);
        a0 = fmaf(wc, hc0, a0); a1 = fmaf(wc, hc1, a1);
        a0 = fmaf(wd, hd0, a0); a1 = fmaf(wd, hd1, a1);
    }
    for (; j < jend; j++) {
        int s = __ldg(&d_csrc[j]);
        float w = __ldg(&d_dis[s]) * di;
        a0 = fmaf(w, __ldg(&hin[(long long)s * 64 + lane]), a0);
        a1 = fmaf(w, __ldg(&hin[(long long)s * 64 + lane + 32]), a1);
    }

    a0 += __ldg(&bias[lane]);
    a1 += __ldg(&bias[lane + 32]);
    if (do_relu) {
        a0 = fmaxf(a0, 0.f);
        a1 = fmaxf(a1, 0.f);
    }
    hout[(long long)node * 64 + lane] = a0;
    hout[(long long)node * 64 + lane + 32] = a1;
}

// ---------------- global mean pool (batch is sorted -> binary search) -----
__device__ __forceinline__ int lower_bound_b(const void* b, int N, long long v) {
    int lo = 0, hi = N;
    while (lo < hi) {
        int m = (lo + hi) >> 1;
        if (load_batch(b, m) < v) lo = m + 1; else hi = m;
    }
    return lo;
}

// reads final features from d_bufB
__global__ void k_pool(const void* __restrict__ batch, int N) {
    int g = blockIdx.x;
    int start = lower_bound_b(batch, N, (long long)g);
    int end = lower_bound_b(batch, N, (long long)g + 1);
    int f = threadIdx.x & 63;
    int r = threadIdx.x >> 6;   // 0..3
    float acc = 0.f;
    for (int i = start + r; i < end; i += 4)
        acc += d_bufB[(long long)i * 64 + f];
    __shared__ float sh[4][64];
    sh[r][f] = acc;
    __syncthreads();
    if (r == 0) {
        float v = sh[0][f] + sh[1][f] + sh[2][f] + sh[3][f];
        float cnt = (float)(end - start);
        d_pooled[g * 64 + f] = v / fmaxf(cnt, 1.0f);
    }
}

// ---------------- classifier MLP ------------------------------------------
__global__ void k_cls(const float* __restrict__ Wc1, const float* __restrict__ bc1,
                      const float* __restrict__ Wc2, const float* __restrict__ bc2,
                      float* __restrict__ out, int G) {
    int g = threadIdx.x;
    if (g >= G) return;
    float p[64];
#pragma unroll
    for (int k = 0; k < 64; k++) p[k] = d_pooled[g * 64 + k];
    float o0 = bc2[0], o1 = bc2[1];
#pragma unroll
    for (int jj = 0; jj < 32; jj++) {
        float h = bc1[jj];
#pragma unroll
        for (int k = 0; k < 64; k++) h = fmaf(p[k], Wc1[k * 32 + jj], h);
        h = fmaxf(h, 0.f);
        o0 = fmaf(h, Wc2[jj * 2 + 0], o0);
        o1 = fmaf(h, Wc2[jj * 2 + 1], o1);
    }
    out[g * 2 + 0] = o0;
    out[g * 2 + 1] = o1;
}

// ---------------- launch ---------------------------------------------------
extern "C" void kernel_launch(void* const* d_in, const int* in_sizes, int n_in,
                              void* d_out, int out_size) {
    const float* x     = (const float*)d_in[0];
    const void*  ei    = d_in[1];
    const void*  batch = d_in[2];
    const float* W1 = (const float*)d_in[3];
    const float* b1 = (const float*)d_in[4];
    const float* W2 = (const float*)d_in[5];
    const float* b2 = (const float*)d_in[6];
    const float* W3 = (const float*)d_in[7];
    const float* b3 = (const float*)d_in[8];
    const float* Wc1 = (const float*)d_in[9];
    const float* bc1 = (const float*)d_in[10];
    const float* Wc2 = (const float*)d_in[11];
    const float* bc2 = (const float*)d_in[12];
    float* out = (float*)d_out;

    int N = in_sizes[0] / 128;
    int E = in_sizes[1] / 2;
    int G = out_size / 2;

    int nb = (N + 1023) / 1024;

    // dtype detection + CSR build
    k_detect<<<1, 1>>>(ei);
    k_zero_cnt<<<(N + 255) / 256, 256>>>(N);
    k_count<<<(E + 255) / 256, 256>>>(ei, E);
    k_blocksum<<<nb, 256>>>(N);
    k_scanpart<<<1, 128>>>(nb, N, E);
    k_scanblock<<<nb, 1024>>>(N);
    k_fill<<<(E + 255) / 256, 256>>>(ei, E);

    int gemm_blocks = (N + 63) / 64;
    int agg_blocks = (N + 7) / 8;

    // conv1: x @ W1 -> bufA; agg bufA -> bufB (relu)
    k_gemm<<<gemm_blocks, 256>>>(x, 0, 1, W1, N, 128);
    k_agg<<<agg_blocks, 256>>>(1, 2, b1, N, 1);
    // conv2: bufB @ W2 -> bufA; agg bufA -> bufB (relu)
    k_gemm<<<gemm_blocks, 256>>>(nullptr, 2, 1, W2, N, 64);
    k_agg<<<agg_blocks, 256>>>(1, 2, b2, N, 1);
    // conv3: bufB @ W3 -> bufA; agg bufA -> bufB (no relu)
    k_gemm<<<gemm_blocks, 256>>>(nullptr, 2, 1, W3, N, 64);
    k_agg<<<agg_blocks, 256>>>(1, 2, b3, N, 0);

    // pool + classifier
    k_pool<<<G, 256>>>(batch, N);
    k_cls<<<1, 64>>>(Wc1, bc1, Wc2, bc2, out, G);
}

// round 5
// speedup vs baseline: 1.1269x; 1.1269x over previous
#include <cuda_runtime.h>
#include <cuda_bf16.h>

// ---------------- problem constants (fixed by the dataset) ----------------
#define MAXN 100000
#define MAXE 1600000
#define HID 64

// ---------------- device scratch (no allocation allowed) ------------------
__device__ float d_bufA[MAXN * HID];
__device__ float d_bufB[MAXN * HID];
__device__ float d_dis[MAXN];          // deg^{-1/2}
__device__ int   d_cnt[MAXN];          // in-degree (without self loop)
__device__ int   d_off[MAXN + 1];      // CSR offsets
__device__ int   d_cursor[MAXN];       // fill cursors
__device__ int   d_csrc[MAXE];         // CSR: src node per incoming edge slot
__device__ int   d_partials[128];      // scan block partials
__device__ float d_pooled[64 * HID];   // per-graph means
__device__ int   g_is64;               // 1 if index tensors are int64

// ---------------- packed fp32x2 helpers (Blackwell) ------------------------
__device__ __forceinline__ float2 ffma2(float2 a, float2 b, float2 c) {
    float2 d;
    asm("fma.rn.f32x2 %0, %1, %2, %3;"
        : "=l"(reinterpret_cast<unsigned long long&>(d))
        : "l"(reinterpret_cast<unsigned long long&>(a)),
          "l"(reinterpret_cast<unsigned long long&>(b)),
          "l"(reinterpret_cast<unsigned long long&>(c)));
    return d;
}
__device__ __forceinline__ float2 fadd2(float2 a, float2 b) {
    float2 d;
    asm("add.rn.f32x2 %0, %1, %2;"
        : "=l"(reinterpret_cast<unsigned long long&>(d))
        : "l"(reinterpret_cast<unsigned long long&>(a)),
          "l"(reinterpret_cast<unsigned long long&>(b)));
    return d;
}

// ---------------- index dtype detection -----------------------------------
__global__ void k_detect(const void* __restrict__ ei) {
    const long long* p = (const long long*)ei;
    int ok = 1;
#pragma unroll
    for (int i = 0; i < 16; i++) {
        long long v = p[i];
        if (v < 0 || v >= MAXN) ok = 0;
    }
    g_is64 = ok;
}

__device__ __forceinline__ int load_idx(const void* p, long long i) {
    return g_is64 ? (int)((const long long*)p)[i] : ((const int*)p)[i];
}
__device__ __forceinline__ long long load_batch(const void* p, int i) {
    return g_is64 ? ((const long long*)p)[i] : (long long)((const int*)p)[i];
}

// ---------------- CSR build ----------------

__global__ void k_zero_cnt(int N) {
    int i = blockIdx.x * blockDim.x + threadIdx.x;
    if (i < N) d_cnt[i] = 0;
}

__global__ void k_count(const void* __restrict__ ei, int E) {
    int e = blockIdx.x * blockDim.x + threadIdx.x;
    if (e < E) {
        int dst = load_idx(ei, (long long)E + e);
        atomicAdd(&d_cnt[dst], 1);
    }
}

// per-1024 block sums + dis = rsqrt(deg+1)
__global__ void k_blocksum(int N) {
    __shared__ int sh[256];
    int b = blockIdx.x, t = threadIdx.x;
    int base = b * 1024;
    int s = 0;
#pragma unroll
    for (int i = 0; i < 4; i++) {
        int idx = base + t + i * 256;
        if (idx < N) {
            int c = d_cnt[idx];
            s += c;
            d_dis[idx] = rsqrtf((float)(c + 1));
        }
    }
    sh[t] = s;
    __syncthreads();
    for (int o = 128; o > 0; o >>= 1) {
        if (t < o) sh[t] += sh[t + o];
        __syncthreads();
    }
    if (t == 0) d_partials[b] = sh[0];
}

__global__ void k_scanpart(int nb, int N, int E) {
    __shared__ int sh[128];
    int t = threadIdx.x;
    sh[t] = (t < nb) ? d_partials[t] : 0;
    __syncthreads();
    for (int o = 1; o < 128; o <<= 1) {
        int v = (t >= o) ? sh[t - o] : 0;
        __syncthreads();
        sh[t] += v;
        __syncthreads();
    }
    if (t < nb) d_partials[t] = (t == 0) ? 0 : sh[t - 1];
    if (t == 0) d_off[N] = E;
}

__global__ void k_scanblock(int N) {
    __shared__ int sh[1024];
    int b = blockIdx.x, t = threadIdx.x;
    int gid = b * 1024 + t;
    int v = (gid < N) ? d_cnt[gid] : 0;
    sh[t] = v;
    __syncthreads();
    for (int o = 1; o < 1024; o <<= 1) {
        int u = (t >= o) ? sh[t - o] : 0;
        __syncthreads();
        sh[t] += u;
        __syncthreads();
    }
    if (gid < N) {
        int excl = sh[t] - v + d_partials[b];
        d_off[gid] = excl;
        d_cursor[gid] = excl;
    }
}

__global__ void k_fill(const void* __restrict__ ei, int E) {
    int e = blockIdx.x * blockDim.x + threadIdx.x;
    if (e < E) {
        int dst = load_idx(ei, (long long)E + e);
        int src = load_idx(ei, e);
        int p = atomicAdd(&d_cursor[dst], 1);
        d_csrc[p] = src;
    }
}

// ---------------- GEMM: C[row] = dis[row] * (A[row] @ B), B is K x 64 ------
// BM=128, BN=64, BK=16; 256 threads; 8 rows x 4 cols per thread.
// Accumulators are float2 pairs over rows, math via fma.rn.f32x2.
// src: 0 external A, 1 d_bufA, 2 d_bufB; dst: 1 d_bufA, 2 d_bufB
__global__ __launch_bounds__(256) void k_gemm(const float* __restrict__ Aext,
                                              const int src, const int dst,
                                              const float* __restrict__ B,
                                              int N, int K) {
    const float* A = (src == 0) ? Aext : (src == 1 ? d_bufA : d_bufB);
    float* C = (dst == 1) ? d_bufA : d_bufB;

    __shared__ float As[16][128];
    __shared__ float Bs[16][64];
    int block_row = blockIdx.x * 128;
    int t = threadIdx.x;
    int tx = t & 15;          // col group: cols tx*4 .. tx*4+3
    int ty = t >> 4;          // row group: rows ty*8 .. ty*8+7

    float2 acc[4][4];         // [c][row_pair]
#pragma unroll
    for (int c = 0; c < 4; c++)
#pragma unroll
        for (int rp = 0; rp < 4; rp++) acc[c][rp] = make_float2(0.f, 0.f);

    for (int k0 = 0; k0 < K; k0 += 16) {
        // A tile: 128 rows x 16 k (transposed into As[kk][m]); 8 floats/thread
        {
            int m = t >> 1;            // 0..127
            int kk = (t & 1) * 8;      // 0 or 8
            int row = block_row + m;
            float4 v0 = make_float4(0.f, 0.f, 0.f, 0.f);
            float4 v1 = make_float4(0.f, 0.f, 0.f, 0.f);
            if (row < N) {
                v0 = *(const float4*)&A[(long long)row * K + k0 + kk];
                v1 = *(const float4*)&A[(long long)row * K + k0 + kk + 4];
            }
            As[kk + 0][m] = v0.x; As[kk + 1][m] = v0.y;
            As[kk + 2][m] = v0.z; As[kk + 3][m] = v0.w;
            As[kk + 4][m] = v1.x; As[kk + 5][m] = v1.y;
            As[kk + 6][m] = v1.z; As[kk + 7][m] = v1.w;
        }
        // B tile: 16 x 64
        {
            int kk = t >> 4;           // 0..15
            int n = (t & 15) * 4;
            *(float4*)&Bs[kk][n] = *(const float4*)&B[(k0 + kk) * 64 + n];
        }
        __syncthreads();

#pragma unroll
        for (int kk = 0; kk < 16; kk++) {
            float4 alo = *(float4*)&As[kk][ty * 8];
            float4 ahi = *(float4*)&As[kk][ty * 8 + 4];
            float2 a2[4] = {{alo.x, alo.y}, {alo.z, alo.w},
                            {ahi.x, ahi.y}, {ahi.z, ahi.w}};
            float4 b4 = *(float4*)&Bs[kk][tx * 4];
            float bb[4] = {b4.x, b4.y, b4.z, b4.w};
#pragma unroll
            for (int c = 0; c < 4; c++) {
                float2 bc = make_float2(bb[c], bb[c]);
#pragma unroll
                for (int rp = 0; rp < 4; rp++)
                    acc[c][rp] = ffma2(a2[rp], bc, acc[c][rp]);
            }
        }
        __syncthreads();
    }

    // epilogue: prescale by dis[row], write h' = dis * (A@W)
#pragma unroll
    for (int r = 0; r < 8; r++) {
        int row = block_row + ty * 8 + r;
        if (row < N) {
            float s = d_dis[row];
            int rp = r >> 1;
            float4 o;
            if (r & 1) {
                o.x = s * acc[0][rp].y; o.y = s * acc[1][rp].y;
                o.z = s * acc[2][rp].y; o.w = s * acc[3][rp].y;
            } else {
                o.x = s * acc[0][rp].x; o.y = s * acc[1][rp].x;
                o.z = s * acc[2][rp].x; o.w = s * acc[3][rp].x;
            }
            *(float4*)&C[(long long)row * 64 + tx * 4] = o;
        }
    }
}

// ---------------- aggregation --------------------------------------------
// h' = dis * (A@W) already prescaled by GEMM epilogue.
// out[i] = dis[i] * (h'[i] + sum_{j in N(i)} h'[j]) + bias   (+ relu)
// one warp per node; lane handles features (2*lane, 2*lane+1) as float2.
__global__ __launch_bounds__(256) void k_agg(const int src, const int dst,
                                             const float* __restrict__ bias,
                                             int N, const int do_relu) {
    const float2* hin = (const float2*)((src == 1) ? d_bufA : d_bufB);
    float2* hout = (float2*)((dst == 1) ? d_bufA : d_bufB);

    int node = blockIdx.x * 8 + (threadIdx.x >> 5);
    if (node >= N) return;
    int lane = threadIdx.x & 31;

    float2 acc = __ldg(&hin[(long long)node * 32 + lane]);  // self term
    int j = __ldg(&d_off[node]);
    int jend = __ldg(&d_off[node + 1]);

    for (; j + 8 <= jend; j += 8) {
        int s0 = __ldg(&d_csrc[j + 0]);
        int s1 = __ldg(&d_csrc[j + 1]);
        int s2 = __ldg(&d_csrc[j + 2]);
        int s3 = __ldg(&d_csrc[j + 3]);
        int s4 = __ldg(&d_csrc[j + 4]);
        int s5 = __ldg(&d_csrc[j + 5]);
        int s6 = __ldg(&d_csrc[j + 6]);
        int s7 = __ldg(&d_csrc[j + 7]);
        float2 v0 = __ldg(&hin[(long long)s0 * 32 + lane]);
        float2 v1 = __ldg(&hin[(long long)s1 * 32 + lane]);
        float2 v2 = __ldg(&hin[(long long)s2 * 32 + lane]);
        float2 v3 = __ldg(&hin[(long long)s3 * 32 + lane]);
        float2 v4 = __ldg(&hin[(long long)s4 * 32 + lane]);
        float2 v5 = __ldg(&hin[(long long)s5 * 32 + lane]);
        float2 v6 = __ldg(&hin[(long long)s6 * 32 + lane]);
        float2 v7 = __ldg(&hin[(long long)s7 * 32 + lane]);
        float2 t0 = fadd2(v0, v1);
        float2 t1 = fadd2(v2, v3);
        float2 t2 = fadd2(v4, v5);
        float2 t3 = fadd2(v6, v7);
        float2 u0 = fadd2(t0, t1);
        float2 u1 = fadd2(t2, t3);
        acc = fadd2(acc, fadd2(u0, u1));
    }
    for (; j < jend; j++) {
        int s = __ldg(&d_csrc[j]);
        acc = fadd2(acc, __ldg(&hin[(long long)s * 32 + lane]));
    }

    float di = d_dis[node];
    float2 b = __ldg(&((const float2*)bias)[lane]);
    float2 o;
    o.x = fmaf(di, acc.x, b.x);
    o.y = fmaf(di, acc.y, b.y);
    if (do_relu) {
        o.x = fmaxf(o.x, 0.f);
        o.y = fmaxf(o.y, 0.f);
    }
    hout[(long long)node * 32 + lane] = o;
}

// ---------------- global mean pool (batch is sorted -> binary search) -----
__device__ __forceinline__ int lower_bound_b(const void* b, int N, long long v) {
    int lo = 0, hi = N;
    while (lo < hi) {
        int m = (lo + hi) >> 1;
        if (load_batch(b, m) < v) lo = m + 1; else hi = m;
    }
    return lo;
}

// reads final features from d_bufB
__global__ void k_pool(const void* __restrict__ batch, int N) {
    int g = blockIdx.x;
    int start = lower_bound_b(batch, N, (long long)g);
    int end = lower_bound_b(batch, N, (long long)g + 1);
    int f = threadIdx.x & 63;
    int r = threadIdx.x >> 6;   // 0..3
    float acc = 0.f;
    for (int i = start + r; i < end; i += 4)
        acc += d_bufB[(long long)i * 64 + f];
    __shared__ float sh[4][64];
    sh[r][f] = acc;
    __syncthreads();
    if (r == 0) {
        float v = sh[0][f] + sh[1][f] + sh[2][f] + sh[3][f];
        float cnt = (float)(end - start);
        d_pooled[g * 64 + f] = v / fmaxf(cnt, 1.0f);
    }
}

// ---------------- classifier MLP ------------------------------------------
__global__ void k_cls(const float* __restrict__ Wc1, const float* __restrict__ bc1,
                      const float* __restrict__ Wc2, const float* __restrict__ bc2,
                      float* __restrict__ out, int G) {
    int g = threadIdx.x;
    if (g >= G) return;
    float p[64];
#pragma unroll
    for (int k = 0; k < 64; k++) p[k] = d_pooled[g * 64 + k];
    float o0 = bc2[0], o1 = bc2[1];
#pragma unroll
    for (int jj = 0; jj < 32; jj++) {
        float h = bc1[jj];
#pragma unroll
        for (int k = 0; k < 64; k++) h = fmaf(p[k], Wc1[k * 32 + jj], h);
        h = fmaxf(h, 0.f);
        o0 = fmaf(h, Wc2[jj * 2 + 0], o0);
        o1 = fmaf(h, Wc2[jj * 2 + 1], o1);
    }
    out[g * 2 + 0] = o0;
    out[g * 2 + 1] = o1;
}

// ---------------- launch ---------------------------------------------------
extern "C" void kernel_launch(void* const* d_in, const int* in_sizes, int n_in,
                              void* d_out, int out_size) {
    const float* x     = (const float*)d_in[0];
    const void*  ei    = d_in[1];
    const void*  batch = d_in[2];
    const float* W1 = (const float*)d_in[3];
    const float* b1 = (const float*)d_in[4];
    const float* W2 = (const float*)d_in[5];
    const float* b2 = (const float*)d_in[6];
    const float* W3 = (const float*)d_in[7];
    const float* b3 = (const float*)d_in[8];
    const float* Wc1 = (const float*)d_in[9];
    const float* bc1 = (const float*)d_in[10];
    const float* Wc2 = (const float*)d_in[11];
    const float* bc2 = (const float*)d_in[12];
    float* out = (float*)d_out;

    int N = in_sizes[0] / 128;
    int E = in_sizes[1] / 2;
    int G = out_size / 2;

    int nb = (N + 1023) / 1024;

    // dtype detection + CSR build (computes d_dis before GEMMs)
    k_detect<<<1, 1>>>(ei);
    k_zero_cnt<<<(N + 255) / 256, 256>>>(N);
    k_count<<<(E + 255) / 256, 256>>>(ei, E);
    k_blocksum<<<nb, 256>>>(N);
    k_scanpart<<<1, 128>>>(nb, N, E);
    k_scanblock<<<nb, 1024>>>(N);
    k_fill<<<(E + 255) / 256, 256>>>(ei, E);

    int gemm_blocks = (N + 127) / 128;
    int agg_blocks = (N + 7) / 8;

    // conv1: h' = dis*(x @ W1) -> bufA; agg bufA -> bufB (relu)
    k_gemm<<<gemm_blocks, 256>>>(x, 0, 1, W1, N, 128);
    k_agg<<<agg_blocks, 256>>>(1, 2, b1, N, 1);
    // conv2
    k_gemm<<<gemm_blocks, 256>>>(nullptr, 2, 1, W2, N, 64);
    k_agg<<<agg_blocks, 256>>>(1, 2, b2, N, 1);
    // conv3 (no relu)
    k_gemm<<<gemm_blocks, 256>>>(nullptr, 2, 1, W3, N, 64);
    k_agg<<<agg_blocks, 256>>>(1, 2, b3, N, 0);

    // pool + classifier
    k_pool<<<G, 256>>>(batch, N);
    k_cls<<<1, 64>>>(Wc1, bc1, Wc2, bc2, out, G);
}